// round 1
// baseline (speedup 1.0000x reference)
#include <cuda_runtime.h>

#define MN 50000      // nodes
#define EN 800000     // edges
#define FIN 32
#define NB 4
#define KORD 4
#define CH 32
#define ROWLEN 128    // NB*FIN floats per node row

// ---------------- device scratch (static, no allocations) ----------------
__device__ float  d_T0[MN * ROWLEN];
__device__ float  d_T1[MN * ROWLEN];
__device__ float  d_T2[MN * ROWLEN];
__device__ float  d_T3[MN * ROWLEN];
__device__ float2 d_ev[EN];          // {val, col-as-bits} in CSR order
__device__ int    d_cnt[MN];
__device__ int    d_cur[MN];
__device__ int    d_ptr[MN + 1];

// ---------------- CSR build ----------------
__global__ void zero_cnt_k() {
    int i = blockIdx.x * blockDim.x + threadIdx.x;
    if (i < MN) d_cnt[i] = 0;
}

__global__ void hist_k(const int* __restrict__ rows) {
    int i = blockIdx.x * blockDim.x + threadIdx.x;
    if (i < EN) atomicAdd(&d_cnt[rows[i]], 1);
}

// single-block exclusive scan over d_cnt -> d_ptr, d_cur
__global__ void scan_k() {
    __shared__ int wsum[32];
    const int PT = 49;                    // ceil(50000/1024)
    int t = threadIdx.x, lane = t & 31, wid = t >> 5;
    int base = t * PT;
    // pass 1: thread-local total
    int s = 0;
    for (int i = 0; i < PT; i++) {
        int idx = base + i;
        s += (idx < MN) ? d_cnt[idx] : 0;
    }
    // warp inclusive scan of thread totals
    int v = s;
    #pragma unroll
    for (int o = 1; o < 32; o <<= 1) {
        int u = __shfl_up_sync(0xffffffffu, v, o);
        if (lane >= o) v += u;
    }
    if (lane == 31) wsum[wid] = v;
    __syncthreads();
    if (t == 0) {
        int a = 0;
        for (int j = 0; j < 32; j++) { int x = wsum[j]; wsum[j] = a; a += x; }
    }
    __syncthreads();
    int excl = wsum[wid] + (v - s);       // exclusive prefix for this thread
    // pass 2: write running prefix
    int run = excl;
    for (int i = 0; i < PT; i++) {
        int idx = base + i;
        if (idx < MN) {
            int c = d_cnt[idx];
            d_ptr[idx] = run;
            d_cur[idx] = run;
            run += c;
        }
    }
    if (t == 1023) d_ptr[MN] = run;       // == EN
}

__global__ void scatter_k(const float* __restrict__ vals,
                          const int* __restrict__ rows,
                          const int* __restrict__ cols) {
    int i = blockIdx.x * blockDim.x + threadIdx.x;
    if (i < EN) {
        int r = rows[i];
        int p = atomicAdd(&d_cur[r], 1);
        d_ev[p] = make_float2(vals[i], __int_as_float(cols[i]));
    }
}

// ---------------- T0 = transpose(x) into [m][n*32+f] layout ----------------
__global__ void build_x0_k(const float* __restrict__ x) {
    int m = blockIdx.x * (blockDim.x >> 5) + (threadIdx.x >> 5);
    if (m >= MN) return;
    int lane = threadIdx.x & 31;
    int j = lane * 4;
    int n = j >> 5, f = j & 31;
    float4 v = *(const float4*)(x + (n * MN + m) * FIN + f);
    *(float4*)(d_T0 + m * ROWLEN + j) = v;
}

// ---------------- SpMM: Xout = alpha*(L @ Xin) - Xsub (Xsub may be null) ----------------
__global__ void spmm_k(const float* __restrict__ Xin,
                       const float* __restrict__ Xsub,
                       float* __restrict__ Xout,
                       float alpha) {
    int r = blockIdx.x * (blockDim.x >> 5) + (threadIdx.x >> 5);
    if (r >= MN) return;
    int lane = threadIdx.x & 31;
    int beg = d_ptr[r], end = d_ptr[r + 1];
    float ax = 0.f, ay = 0.f, az = 0.f, aw = 0.f;

    int e = beg;
    // unroll-by-2 for MLP on the dependent ev->gather chain
    for (; e + 2 <= end; e += 2) {
        float2 a = __ldg(&d_ev[e]);
        float2 b = __ldg(&d_ev[e + 1]);
        const float4 xa = *(const float4*)(Xin + __float_as_int(a.y) * ROWLEN + lane * 4);
        const float4 xb = *(const float4*)(Xin + __float_as_int(b.y) * ROWLEN + lane * 4);
        ax = fmaf(a.x, xa.x, ax); ay = fmaf(a.x, xa.y, ay);
        az = fmaf(a.x, xa.z, az); aw = fmaf(a.x, xa.w, aw);
        ax = fmaf(b.x, xb.x, ax); ay = fmaf(b.x, xb.y, ay);
        az = fmaf(b.x, xb.z, az); aw = fmaf(b.x, xb.w, aw);
    }
    if (e < end) {
        float2 a = __ldg(&d_ev[e]);
        const float4 xa = *(const float4*)(Xin + __float_as_int(a.y) * ROWLEN + lane * 4);
        ax = fmaf(a.x, xa.x, ax); ay = fmaf(a.x, xa.y, ay);
        az = fmaf(a.x, xa.z, az); aw = fmaf(a.x, xa.w, aw);
    }

    float4 o;
    if (Xsub) {
        float4 s = *(const float4*)(Xsub + r * ROWLEN + lane * 4);
        o.x = fmaf(alpha, ax, -s.x);
        o.y = fmaf(alpha, ay, -s.y);
        o.z = fmaf(alpha, az, -s.z);
        o.w = fmaf(alpha, aw, -s.w);
    } else {
        o = make_float4(ax, ay, az, aw);
    }
    *(float4*)(Xout + r * ROWLEN + lane * 4) = o;
}

// ---------------- fused GEMM + bias + relu ----------------
// out[n,m,c] = relu( bias[c] + sum_{f,k} T_k[m][n*32+f] * W[f*4+k][c] )
__global__ void gemm_k(const float* __restrict__ Wg,
                       const float* __restrict__ bias,
                       float* __restrict__ out) {
    __shared__ float Ws[KORD * FIN * CH];   // 4096 floats = 16 KB
    __shared__ float bsm[CH];
    int tid = threadIdx.x;
    for (int i = tid; i < KORD * FIN * CH; i += blockDim.x) Ws[i] = Wg[i];
    if (tid < CH) bsm[tid] = bias[tid];
    __syncthreads();

    int nm = blockIdx.x * blockDim.x + tid;
    if (nm >= NB * MN) return;
    int n = nm / MN;
    int m = nm - n * MN;
    int base = m * ROWLEN + n * FIN;

    float acc[CH];
    #pragma unroll
    for (int c = 0; c < CH; c++) acc[c] = 0.f;

    #pragma unroll 1
    for (int k = 0; k < KORD; k++) {
        const float* T = (k == 0) ? d_T0 : (k == 1) ? d_T1 : (k == 2) ? d_T2 : d_T3;
        #pragma unroll
        for (int q = 0; q < 8; q++) {
            float4 xq = *(const float4*)(T + base + q * 4);
            #pragma unroll
            for (int ff = 0; ff < 4; ff++) {
                float xf = (ff == 0) ? xq.x : (ff == 1) ? xq.y : (ff == 2) ? xq.z : xq.w;
                const float4* wr = (const float4*)(Ws + ((q * 4 + ff) * KORD + k) * CH);
                #pragma unroll
                for (int c4 = 0; c4 < 8; c4++) {
                    float4 w = wr[c4];
                    acc[c4 * 4 + 0] = fmaf(xf, w.x, acc[c4 * 4 + 0]);
                    acc[c4 * 4 + 1] = fmaf(xf, w.y, acc[c4 * 4 + 1]);
                    acc[c4 * 4 + 2] = fmaf(xf, w.z, acc[c4 * 4 + 2]);
                    acc[c4 * 4 + 3] = fmaf(xf, w.w, acc[c4 * 4 + 3]);
                }
            }
        }
    }

    float* op = out + (size_t)nm * CH;
    #pragma unroll
    for (int c4 = 0; c4 < 8; c4++) {
        float4 r;
        r.x = fmaxf(acc[c4 * 4 + 0] + bsm[c4 * 4 + 0], 0.f);
        r.y = fmaxf(acc[c4 * 4 + 1] + bsm[c4 * 4 + 1], 0.f);
        r.z = fmaxf(acc[c4 * 4 + 2] + bsm[c4 * 4 + 2], 0.f);
        r.w = fmaxf(acc[c4 * 4 + 3] + bsm[c4 * 4 + 3], 0.f);
        *(float4*)(op + c4 * 4) = r;
    }
}

// ---------------- launch ----------------
extern "C" void kernel_launch(void* const* d_in, const int* in_sizes, int n_in,
                              void* d_out, int out_size) {
    const float* x     = (const float*)d_in[0];
    const float* lvals = (const float*)d_in[1];
    const float* wk    = (const float*)d_in[2];
    const float* bias  = (const float*)d_in[3];
    const int*   rows  = (const int*)d_in[4];
    const int*   cols  = (const int*)d_in[5];
    float* out = (float*)d_out;

    float *t0, *t1, *t2, *t3;
    cudaGetSymbolAddress((void**)&t0, d_T0);
    cudaGetSymbolAddress((void**)&t1, d_T1);
    cudaGetSymbolAddress((void**)&t2, d_T2);
    cudaGetSymbolAddress((void**)&t3, d_T3);

    // CSR build
    zero_cnt_k<<<(MN + 255) / 256, 256>>>();
    hist_k<<<(EN + 255) / 256, 256>>>(rows);
    scan_k<<<1, 1024>>>();
    scatter_k<<<(EN + 255) / 256, 256>>>(lvals, rows, cols);

    // T0 = transposed x
    build_x0_k<<<(MN + 7) / 8, 256>>>(x);

    // Chebyshev recurrence
    spmm_k<<<(MN + 7) / 8, 256>>>(t0, nullptr, t1, 1.0f);   // T1 = L T0
    spmm_k<<<(MN + 7) / 8, 256>>>(t1, t0, t2, 2.0f);        // T2 = 2 L T1 - T0
    spmm_k<<<(MN + 7) / 8, 256>>>(t2, t1, t3, 2.0f);        // T3 = 2 L T2 - T1

    // dense projection + bias + relu
    gemm_k<<<(NB * MN + 255) / 256, 256>>>(wk, bias, out);
}